// round 10
// baseline (speedup 1.0000x reference)
#include <cuda_runtime.h>
#include <cuda_bf16.h>
#include <cuda_fp16.h>
#include <cstdint>

#define N_NODES 100000
#define D 128
#define CSR_STRIDE 128
#define NT ((N_NODES + 63) / 64)     // 1563 tiles
#define GRID_P 592                   // 148 SMs x 4 CTAs

// ---------------------------------------------------------------------------
// Scratch (__device__ globals: allocation-free rule)
// ---------------------------------------------------------------------------
__device__ __align__(128) float  g_h[(size_t)N_NODES * D];             // 51.2 MB
__device__ __align__(128) __half g_feat_h[(size_t)N_NODES * D];        // 25.6 MB
__device__ __align__(128) __half g_h_half[(size_t)N_NODES * D];        // 25.6 MB
__device__ __align__(128) int    g_cur[N_NODES + 8];                   // counters + 2 tile ctrs
__device__ __align__(128) int    g_csr[(size_t)N_NODES * CSR_STRIDE];  // 51.2 MB
__device__ __align__(16)  float  g_wperm[2 * 16 * 2048];

#define FMA_F32X2(d, a, b) \
    asm("fma.rn.f32x2 %0, %1, %2, %0;" : "+l"(d) : "l"(a), "l"(b))
#define UNPACK_F32X2(lo, hi, in) \
    asm("mov.b64 {%0, %1}, %2;" : "=f"(lo), "=f"(hi) : "l"(in))

// ---------------------------------------------------------------------------
// Prep: weight permutation + feat fp32 -> fp16
// ---------------------------------------------------------------------------
#define NW_PREP (2 * 16 * 2048)
#define NC_PREP ((N_NODES * D) / 2)

__global__ void prep_kernel(const float* __restrict__ Ws0, const float* __restrict__ Wn0,
                            const float* __restrict__ Ws1, const float* __restrict__ Wn1,
                            const float* __restrict__ feat)
{
    int gid = blockIdx.x * blockDim.x + threadIdx.x;
    if (gid < NW_PREP) {
        int l  = gid >> 15;
        int r  = gid & 32767;
        int kc = r >> 11;
        int p  = r & 2047;
        int kk = p >> 7;
        int q  = p & 127;
        int lane = q >> 2;
        int g    = q & 3;
        int c = g * 32 + lane;
        int k = kc * 16 + kk;
        const float* Wsrc = (l == 0) ? ((k < 128) ? Ws0 : Wn0)
                                     : ((k < 128) ? Ws1 : Wn1);
        g_wperm[gid] = Wsrc[(size_t)(k & 127) * 128 + c];
    } else {
        int i = gid - NW_PREP;
        if (i < NC_PREP) {
            float2 f = reinterpret_cast<const float2*>(feat)[i];
            reinterpret_cast<__half2*>(g_feat_h)[i] = __float22half2_rn(f);
        }
    }
}

// ---------------------------------------------------------------------------
// CSR fill (fixed stride). cur zeroed beforehand; becomes in-degree.
// ---------------------------------------------------------------------------
__global__ void fill_kernel(const int* __restrict__ src, const int* __restrict__ dst,
                            int* __restrict__ cur, int* __restrict__ csr, int n_edges)
{
    int i = blockIdx.x * blockDim.x + threadIdx.x;
    if (i < n_edges) {
        int d = dst[i];
        int pos = atomicAdd(cur + d, 1);
        if (pos < CSR_STRIDE)
            csr[(size_t)d * CSR_STRIDE + pos] = src[i];
    }
}

// ---------------------------------------------------------------------------
// Persistent fused layer kernel, work-stealing via atomic tile counter.
//   Phase 1: pipelined fp16 gather (next batch's indices prefetched while
//            current batch's features are in flight).
//   Phase 2: K=256 f32x2 GEMM (unchanged core).
// ---------------------------------------------------------------------------
#define AS_STRIDE 36
#define MS_STRIDE 132
#define DYN_FLOATS (64 * MS_STRIDE + 64 * AS_STRIDE + 2048)
#define DYN_BYTES  (DYN_FLOATS * 4)    // 51200

#define ACCUM_H(u, acc) do {                                                     \
    float2 _a = __half22float2(*reinterpret_cast<__half2*>(&(u).x));             \
    float2 _b = __half22float2(*reinterpret_cast<__half2*>(&(u).y));             \
    (acc).x += _a.x; (acc).y += _a.y; (acc).z += _b.x; (acc).w += _b.y;          \
} while (0)

template <bool FUSE_LN>
__global__ void __launch_bounds__(256, 4) sage_fused_kernel(
    const float*  __restrict__ A,
    const __half* __restrict__ Ah,
    const int*    __restrict__ csr,
    const int*    __restrict__ deg,
    const int*    __restrict__ in_deg,
    int*          __restrict__ tile_ctr,   // work-stealing counter
    const float*  __restrict__ Wp_g,
    const float*  __restrict__ bias,
    const float*  __restrict__ ln_g,
    const float*  __restrict__ ln_b,
    float*        __restrict__ Out,
    __half*       __restrict__ OutH)
{
    extern __shared__ __align__(16) float dynf[];
    float* smsg = dynf;
    float* As2  = dynf + 64 * MS_STRIDE;
    float* Wp   = As2 + 64 * AS_STRIDE;
    __shared__ int stile;

    const int t    = threadIdx.x;
    const int tx   = t & 31;
    const int ty   = t >> 5;
    const int lr   = t >> 2;
    const int lk4  = (t & 3) << 2;

    float bia[4], lg[4], lb[4];
#pragma unroll
    for (int c = 0; c < 4; ++c) {
        int col = tx + 32 * c;
        bia[c] = __ldg(bias + col);
        if (FUSE_LN) { lg[c] = __ldg(ln_g + col); lb[c] = __ldg(ln_b + col); }
    }

    for (;;) {
        if (t == 0) stile = atomicAdd(tile_ctr, 1);
        __syncthreads();
        const int tile = stile;
        if (tile >= NT) break;
        const int row0 = tile * 64;

        // ================= Phase 1: pipelined fp16 gather =================
        {
            const int lane4 = tx * 4;    // half-index (8B per lane)
#pragma unroll 1
            for (int jp = 0; jp < 8; jp += 2) {
                const int gr0 = row0 + ty * 8 + jp;
                const int gr1 = gr0 + 1;
                const bool ok0 = gr0 < N_NODES;
                const bool ok1 = gr1 < N_NODES;
                int cnt0 = ok0 ? __ldg(deg + gr0) : 0;
                int cnt1 = ok1 ? __ldg(deg + gr1) : 0;
                if (cnt0 > CSR_STRIDE) cnt0 = CSR_STRIDE;
                if (cnt1 > CSR_STRIDE) cnt1 = CSR_STRIDE;
                const int* p0 = csr + (size_t)gr0 * CSR_STRIDE;
                const int* p1 = csr + (size_t)gr1 * CSR_STRIDE;

                float4 acc0 = make_float4(0.f, 0.f, 0.f, 0.f);
                float4 acc1 = make_float4(0.f, 0.f, 0.f, 0.f);
                const int nb0 = cnt0 >> 2;
                const int nb1 = cnt1 >> 2;
                const int nbm = max(nb0, nb1);

                int4 n0 = make_int4(0, 0, 0, 0), n1 = n0;
                if (nb0 > 0) n0 = *reinterpret_cast<const int4*>(p0);
                if (nb1 > 0) n1 = *reinterpret_cast<const int4*>(p1);

#pragma unroll 1
                for (int b = 0; b < nbm; ++b) {
                    const int4 c0 = n0, c1 = n1;
                    const bool d0 = b < nb0, d1 = b < nb1;
                    uint2 u00, u01, u02, u03, u10, u11, u12, u13;
                    if (d0) {   // issue 4 independent feature loads
                        u00 = *reinterpret_cast<const uint2*>(Ah + (size_t)c0.x * D + lane4);
                        u01 = *reinterpret_cast<const uint2*>(Ah + (size_t)c0.y * D + lane4);
                        u02 = *reinterpret_cast<const uint2*>(Ah + (size_t)c0.z * D + lane4);
                        u03 = *reinterpret_cast<const uint2*>(Ah + (size_t)c0.w * D + lane4);
                    }
                    if (d1) {
                        u10 = *reinterpret_cast<const uint2*>(Ah + (size_t)c1.x * D + lane4);
                        u11 = *reinterpret_cast<const uint2*>(Ah + (size_t)c1.y * D + lane4);
                        u12 = *reinterpret_cast<const uint2*>(Ah + (size_t)c1.z * D + lane4);
                        u13 = *reinterpret_cast<const uint2*>(Ah + (size_t)c1.w * D + lane4);
                    }
                    // prefetch NEXT batch's indices (independent of feats)
                    if (b + 1 < nb0) n0 = *reinterpret_cast<const int4*>(p0 + (b + 1) * 4);
                    if (b + 1 < nb1) n1 = *reinterpret_cast<const int4*>(p1 + (b + 1) * 4);
                    if (d0) { ACCUM_H(u00, acc0); ACCUM_H(u01, acc0);
                              ACCUM_H(u02, acc0); ACCUM_H(u03, acc0); }
                    if (d1) { ACCUM_H(u10, acc1); ACCUM_H(u11, acc1);
                              ACCUM_H(u12, acc1); ACCUM_H(u13, acc1); }
                }
                for (int i = nb0 * 4; i < cnt0; ++i) {
                    int s = __ldg(p0 + i);
                    uint2 u = *reinterpret_cast<const uint2*>(Ah + (size_t)s * D + lane4);
                    ACCUM_H(u, acc0);
                }
                for (int i = nb1 * 4; i < cnt1; ++i) {
                    int s = __ldg(p1 + i);
                    uint2 u = *reinterpret_cast<const uint2*>(Ah + (size_t)s * D + lane4);
                    ACCUM_H(u, acc1);
                }

                if (ok0) {
                    float inv = 1.0f / (float)max(__ldg(in_deg + gr0), 1);
                    acc0.x *= inv; acc0.y *= inv; acc0.z *= inv; acc0.w *= inv;
                }
                if (ok1) {
                    float inv = 1.0f / (float)max(__ldg(in_deg + gr1), 1);
                    acc1.x *= inv; acc1.y *= inv; acc1.z *= inv; acc1.w *= inv;
                }
                *reinterpret_cast<float4*>(smsg + (ty * 8 + jp)     * MS_STRIDE + lane4) = acc0;
                *reinterpret_cast<float4*>(smsg + (ty * 8 + jp + 1) * MS_STRIDE + lane4) = acc1;
            }
        }
        __syncthreads();

        // ================= Phase 2: K=256 f32x2 GEMM =================
        const int grow_l = row0 + lr;
        const bool okl = grow_l < N_NODES;

        unsigned long long acc[8][2];
#pragma unroll
        for (int j = 0; j < 8; ++j) { acc[j][0] = 0ull; acc[j][1] = 0ull; }

        float4 a4 = okl ? *reinterpret_cast<const float4*>(A + (size_t)grow_l * 128 + lk4)
                        : make_float4(0.f, 0.f, 0.f, 0.f);

#pragma unroll 1
        for (int kc = 0; kc < 16; ++kc) {
            float4 w0 = *reinterpret_cast<const float4*>(Wp_g + kc * 2048 + t * 4);
            float4 w1 = *reinterpret_cast<const float4*>(Wp_g + kc * 2048 + (t + 256) * 4);

            __syncthreads();
            *reinterpret_cast<float4*>(As2 + lr * AS_STRIDE + lk4 * 2) =
                make_float4(a4.x, a4.x, a4.y, a4.y);
            *reinterpret_cast<float4*>(As2 + lr * AS_STRIDE + lk4 * 2 + 4) =
                make_float4(a4.z, a4.z, a4.w, a4.w);
            *reinterpret_cast<float4*>(Wp + t * 4)         = w0;
            *reinterpret_cast<float4*>(Wp + (t + 256) * 4) = w1;

            if (kc < 15) {
                const int kn = kc + 1;
                if (kn < 8) {
                    a4 = okl ? *reinterpret_cast<const float4*>(
                                   A + (size_t)grow_l * 128 + kn * 16 + lk4)
                             : make_float4(0.f, 0.f, 0.f, 0.f);
                } else {
                    a4 = *reinterpret_cast<const float4*>(
                        smsg + lr * MS_STRIDE + (kn - 8) * 16 + lk4);
                }
            }
            __syncthreads();

#pragma unroll
            for (int m = 0; m < 8; ++m) {
                ulonglong2 wA = *reinterpret_cast<const ulonglong2*>(Wp + (2 * m) * 128 + tx * 4);
                ulonglong2 wB = *reinterpret_cast<const ulonglong2*>(Wp + (2 * m + 1) * 128 + tx * 4);
#pragma unroll
                for (int j = 0; j < 8; ++j) {
                    ulonglong2 ap = *reinterpret_cast<const ulonglong2*>(
                        As2 + (ty + j * 8) * AS_STRIDE + m * 4);
                    FMA_F32X2(acc[j][0], ap.x, wA.x);
                    FMA_F32X2(acc[j][1], ap.x, wA.y);
                    FMA_F32X2(acc[j][0], ap.y, wB.x);
                    FMA_F32X2(acc[j][1], ap.y, wB.y);
                }
            }
        }

        // ================= Epilogue =================
#pragma unroll
        for (int j = 0; j < 8; ++j) {
            int grow = row0 + ty + j * 8;
            float v[4];
            UNPACK_F32X2(v[0], v[1], acc[j][0]);
            UNPACK_F32X2(v[2], v[3], acc[j][1]);
#pragma unroll
            for (int c = 0; c < 4; ++c) v[c] += bia[c];

            if (FUSE_LN) {
                float s = v[0] + v[1] + v[2] + v[3];
#pragma unroll
                for (int o = 16; o > 0; o >>= 1) s += __shfl_xor_sync(0xffffffffu, s, o);
                float mu = s * (1.0f / 128.0f);
                float d2 = 0.f;
#pragma unroll
                for (int c = 0; c < 4; ++c) { float dd = v[c] - mu; d2 += dd * dd; }
#pragma unroll
                for (int o = 16; o > 0; o >>= 1) d2 += __shfl_xor_sync(0xffffffffu, d2, o);
                float rstd = rsqrtf(d2 * (1.0f / 128.0f) + 1e-5f);
#pragma unroll
                for (int c = 0; c < 4; ++c) {
                    float y = (v[c] - mu) * rstd * lg[c] + lb[c];
                    v[c] = fmaxf(y, 0.0f);
                }
            }

            if (grow < N_NODES) {
#pragma unroll
                for (int c = 0; c < 4; ++c) {
                    Out[(size_t)grow * 128 + tx + 32 * c] = v[c];
                    if (FUSE_LN)
                        OutH[(size_t)grow * 128 + tx + 32 * c] = __float2half_rn(v[c]);
                }
            }
        }
        // loop: next stolen tile (body syncs protect stile/smsg reuse)
    }
}

// ---------------------------------------------------------------------------
// Launch order: [memset, prep, fill, fused0, fused1] (5th = fused1 for ncu)
// ---------------------------------------------------------------------------
extern "C" void kernel_launch(void* const* d_in, const int* in_sizes, int n_in,
                              void* d_out, int out_size)
{
    const float* feat = (const float*)d_in[0];
    const float* Ws0  = (const float*)d_in[1];
    const float* Wn0  = (const float*)d_in[2];
    const float* b0   = (const float*)d_in[3];
    const float* Ws1  = (const float*)d_in[4];
    const float* Wn1  = (const float*)d_in[5];
    const float* b1   = (const float*)d_in[6];
    const float* lng  = (const float*)d_in[7];
    const float* lnb  = (const float*)d_in[8];
    const int*   esrc = (const int*)d_in[9];
    const int*   edst = (const int*)d_in[10];
    const int*   indeg= (const int*)d_in[11];
    const int n_edges = in_sizes[9];

    float *h = nullptr, *wperm = nullptr;
    __half *feath = nullptr, *hhalf = nullptr;
    int *cur = nullptr, *csr = nullptr;
    cudaGetSymbolAddress((void**)&h,     g_h);
    cudaGetSymbolAddress((void**)&feath, g_feat_h);
    cudaGetSymbolAddress((void**)&hhalf, g_h_half);
    cudaGetSymbolAddress((void**)&cur,   g_cur);
    cudaGetSymbolAddress((void**)&csr,   g_csr);
    cudaGetSymbolAddress((void**)&wperm, g_wperm);

    const int eb          = (n_edges + 255) / 256;
    const int prep_blocks = (NW_PREP + NC_PREP + 255) / 256;

    cudaFuncSetAttribute(sage_fused_kernel<true>,
                         cudaFuncAttributeMaxDynamicSharedMemorySize, DYN_BYTES);
    cudaFuncSetAttribute(sage_fused_kernel<false>,
                         cudaFuncAttributeMaxDynamicSharedMemorySize, DYN_BYTES);

    // (1) zero CSR counters AND the two tile counters (one memset)
    cudaMemsetAsync(cur, 0, (N_NODES + 8) * sizeof(int), 0);
    // (2) weight permutation + feat -> fp16
    prep_kernel<<<prep_blocks, 256>>>(Ws0, Wn0, Ws1, Wn1, feat);
    // (3) fixed-stride CSR fill (cur becomes degree)
    fill_kernel<<<eb, 256>>>(esrc, edst, cur, csr, n_edges);

    // (4) Layer 0 (persistent, work-stealing; emits fp32 + fp16 h)
    sage_fused_kernel<true><<<GRID_P, 256, DYN_BYTES>>>(
        feat, feath, csr, cur, indeg, cur + N_NODES, wperm,
        b0, lng, lnb, h, hhalf);

    // (5) Layer 1  <- profiled launch
    sage_fused_kernel<false><<<GRID_P, 256, DYN_BYTES>>>(
        h, hhalf, csr, cur, indeg, cur + N_NODES + 1, wperm + 16 * 2048,
        b1, lng, lnb, (float*)d_out, nullptr);
}